// round 1
// baseline (speedup 1.0000x reference)
#include <cuda_runtime.h>

// DeepSurvLoss: Cox partial likelihood, N=16384.
//   P_exp = exp(P_risk)
//   P_exp_sum[i] = sum_{j: T[j] > T[i]} P_exp[j]
//   has_risk[i]  = (T[i] < max(T))          (strict > exists)
//   Ef[i] = E[i] * has_risk[i]
//   loss = -sum( log(max(P_exp[i]/(P_exp_sum[i]+EPS), EPS)) * Ef[i] ) / sum(Ef)
//
// Strategy: O(N^2) pairwise masked sum, tiled through shared memory.
// All lanes of a warp iterate the same j sequence -> LDS broadcasts.
// j split into NCHUNK chunks; partials land race-free in g_partial.

#define N_ELEM 16384
#define NCHUNK 8
#define CHUNK  (N_ELEM / NCHUNK)   // 2048
#define TPB    256
#define EPSF   1e-6f

__device__ float2   g_pack[N_ELEM];            // (T[j], P_exp[j])
__device__ float    g_partial[NCHUNK][N_ELEM]; // partial risk-set sums
__device__ unsigned g_tmax_bits;               // max(T) as float bits (T >= 0)

__global__ void k_init() { g_tmax_bits = 0u; }

__global__ void k_pack(const float* __restrict__ P_risk,
                       const float* __restrict__ T) {
    int i = blockIdx.x * blockDim.x + threadIdx.x;
    float t  = T[i];
    float pe = expf(P_risk[i]);
    g_pack[i] = make_float2(t, pe);
    // warp-reduce max(T), one atomic per warp (positive floats: uint order == float order)
    unsigned tb = __float_as_uint(t);
    #pragma unroll
    for (int o = 16; o; o >>= 1)
        tb = max(tb, __shfl_xor_sync(0xffffffffu, tb, o));
    if ((threadIdx.x & 31) == 0)
        atomicMax(&g_tmax_bits, tb);
}

__global__ void __launch_bounds__(TPB) k_main(const float* __restrict__ T) {
    __shared__ float2 tile[CHUNK];              // 16 KB
    const int i = blockIdx.x * TPB + threadIdx.x;
    const int c = blockIdx.y;
    const float Ti = T[i];

    const float2* __restrict__ src = g_pack + c * CHUNK;
    #pragma unroll
    for (int k = threadIdx.x; k < CHUNK; k += TPB)
        tile[k] = src[k];
    __syncthreads();

    float s0 = 0.f, s1 = 0.f, s2 = 0.f, s3 = 0.f;
    #pragma unroll 4
    for (int j = 0; j < CHUNK; j += 4) {
        float2 a = tile[j + 0];
        float2 b = tile[j + 1];
        float2 d = tile[j + 2];
        float2 e = tile[j + 3];
        if (a.x > Ti) s0 += a.y;
        if (b.x > Ti) s1 += b.y;
        if (d.x > Ti) s2 += d.y;
        if (e.x > Ti) s3 += e.y;
    }
    g_partial[c][i] = (s0 + s1) + (s2 + s3);
}

__global__ void __launch_bounds__(1024) k_final(const int* __restrict__ E,
                                                float* __restrict__ out) {
    __shared__ float rednum[32], redden[32];
    float num = 0.f, den = 0.f;
    const float tmax = __uint_as_float(g_tmax_bits);

    for (int i = threadIdx.x; i < N_ELEM; i += 1024) {
        float2 pk = g_pack[i];
        bool ef = (E[i] != 0) && (pk.x < tmax);   // strict: ties at max excluded
        if (ef) {
            float s = 0.f;
            #pragma unroll
            for (int c = 0; c < NCHUNK; c++) s += g_partial[c][i];
            float pt = pk.y / (s + EPSF);
            pt = fmaxf(pt, EPSF);                 // upper clip at max(P_tmp) is a no-op
            num += logf(pt);
            den += 1.0f;
        }
    }
    #pragma unroll
    for (int o = 16; o; o >>= 1) {
        num += __shfl_xor_sync(0xffffffffu, num, o);
        den += __shfl_xor_sync(0xffffffffu, den, o);
    }
    int w = threadIdx.x >> 5, l = threadIdx.x & 31;
    if (l == 0) { rednum[w] = num; redden[w] = den; }
    __syncthreads();
    if (w == 0) {
        num = (l < 32) ? rednum[l] : 0.f;
        den = (l < 32) ? redden[l] : 0.f;
        #pragma unroll
        for (int o = 16; o; o >>= 1) {
            num += __shfl_xor_sync(0xffffffffu, num, o);
            den += __shfl_xor_sync(0xffffffffu, den, o);
        }
        if (l == 0) out[0] = -num / den;
    }
}

extern "C" void kernel_launch(void* const* d_in, const int* in_sizes, int n_in,
                              void* d_out, int out_size) {
    const float* P_risk = (const float*)d_in[0];
    const float* T      = (const float*)d_in[1];
    const int*   E      = (const int*)d_in[2];
    float* out = (float*)d_out;

    k_init<<<1, 1>>>();
    k_pack<<<N_ELEM / TPB, TPB>>>(P_risk, T);
    dim3 grid(N_ELEM / TPB, NCHUNK);
    k_main<<<grid, TPB>>>(T);
    k_final<<<1, 1024>>>(E, out);
}

// round 2
// speedup vs baseline: 1.1245x; 1.1245x over previous
#include <cuda_runtime.h>

// DeepSurvLoss, N=16384. O(N) bucketed counting-sort formulation.
//   P_exp_sum[i] = sum_{j: T[j] > T[i]} exp(P_risk[j])
// Buckets: b = floor(T * 2^14)  (exact, monotone in T since T in [0,1)).
// Cross-bucket part from a suffix scan of per-bucket sums; same-bucket part
// by exact strict comparison over that bucket's (avg 1) members.

#define N_ELEM 16384
#define NB     16384            // buckets; avg occupancy 1
#define SCAN_T 1024
#define PER    (NB / SCAN_T)    // 16 elems per scan thread
#define EPSF   1e-6f

__device__ float    g_pe[N_ELEM];        // exp(P_risk)
__device__ float2   g_sorted[N_ELEM];    // (T, pe) grouped by bucket
__device__ int      g_hist[NB];
__device__ int      g_offs[NB];
__device__ int      g_cursor[NB];
__device__ float    g_bsum[NB];
__device__ float    g_suf[NB];           // sum over buckets strictly greater
__device__ float    g_num, g_den;
__device__ unsigned g_tmax_bits;
__device__ int      g_done = 0;

__device__ __forceinline__ int bucket_of(float t) {
    int b = (int)(t * 16384.0f);         // *2^14 is exact -> monotone
    return b > (NB - 1) ? (NB - 1) : b;
}

__global__ void k_init() {
    int i = blockIdx.x * blockDim.x + threadIdx.x;
    g_hist[i] = 0;
    g_bsum[i] = 0.f;
    if (i == 0) { g_num = 0.f; g_den = 0.f; g_tmax_bits = 0u; }
}

__global__ void k_pack(const float* __restrict__ P_risk,
                       const float* __restrict__ T) {
    int i = blockIdx.x * blockDim.x + threadIdx.x;
    float t  = T[i];
    float pe = expf(P_risk[i]);
    g_pe[i] = pe;
    int b = bucket_of(t);
    atomicAdd(&g_hist[b], 1);
    atomicAdd(&g_bsum[b], pe);
    // warp-reduced max(T); T >= 0 so uint order == float order
    unsigned tb = __float_as_uint(t);
    #pragma unroll
    for (int o = 16; o; o >>= 1)
        tb = max(tb, __shfl_xor_sync(0xffffffffu, tb, o));
    if ((threadIdx.x & 31) == 0)
        atomicMax(&g_tmax_bits, tb);
}

// One block: (a) exclusive prefix scan of g_hist -> g_offs/g_cursor,
//            (b) exclusive prefix scan of REVERSED g_bsum -> g_suf
//            (direct suffix sum of positives; no cancellation).
__global__ void __launch_bounds__(SCAN_T) k_scan() {
    __shared__ int   wsum[32];
    __shared__ float wsumf[32];
    const int t = threadIdx.x, lane = t & 31, w = t >> 5;
    const int base = t * PER;

    // ---- int scan ----
    int loc[PER], run = 0;
    #pragma unroll
    for (int k = 0; k < PER; k++) { loc[k] = run; run += g_hist[base + k]; }
    int inc = run;
    #pragma unroll
    for (int o = 1; o < 32; o <<= 1) {
        int v = __shfl_up_sync(0xffffffffu, inc, o);
        if (lane >= o) inc += v;
    }
    if (lane == 31) wsum[w] = inc;
    __syncthreads();
    if (w == 0) {
        int v = wsum[lane], iv = v;
        #pragma unroll
        for (int o = 1; o < 32; o <<= 1) {
            int u = __shfl_up_sync(0xffffffffu, iv, o);
            if (lane >= o) iv += u;
        }
        wsum[lane] = iv - v;                 // exclusive warp base
    }
    __syncthreads();
    {
        int tbase = wsum[w] + (inc - run);
        #pragma unroll
        for (int k = 0; k < PER; k++) {
            int o = tbase + loc[k];
            g_offs[base + k]   = o;
            g_cursor[base + k] = o;
        }
    }
    __syncthreads();

    // ---- float scan over reversed g_bsum ----
    float locf[PER], runf = 0.f;
    #pragma unroll
    for (int k = 0; k < PER; k++) {
        locf[k] = runf;
        runf += g_bsum[NB - 1 - (base + k)];
    }
    float incf = runf;
    #pragma unroll
    for (int o = 1; o < 32; o <<= 1) {
        float v = __shfl_up_sync(0xffffffffu, incf, o);
        if (lane >= o) incf += v;
    }
    if (lane == 31) wsumf[w] = incf;
    __syncthreads();
    if (w == 0) {
        float v = wsumf[lane], iv = v;
        #pragma unroll
        for (int o = 1; o < 32; o <<= 1) {
            float u = __shfl_up_sync(0xffffffffu, iv, o);
            if (lane >= o) iv += u;
        }
        wsumf[lane] = iv - v;
    }
    __syncthreads();
    {
        float tbase = wsumf[w] + (incf - runf);
        #pragma unroll
        for (int k = 0; k < PER; k++)
            g_suf[NB - 1 - (base + k)] = tbase + locf[k];
    }
}

__global__ void k_scatter(const float* __restrict__ T) {
    int j = blockIdx.x * blockDim.x + threadIdx.x;
    float t = T[j];
    int b = bucket_of(t);
    int pos = atomicAdd(&g_cursor[b], 1);
    g_sorted[pos] = make_float2(t, g_pe[j]);
}

__global__ void __launch_bounds__(256) k_final(const float* __restrict__ T,
                                               const int* __restrict__ E,
                                               float* __restrict__ out) {
    __shared__ float rn[8], rd[8];
    const int i = blockIdx.x * 256 + threadIdx.x;
    const float Ti = T[i];
    const int b = bucket_of(Ti);

    float s = g_suf[b];
    int st = g_offs[b], en = st + g_hist[b];
    for (int m = st; m < en; m++) {
        float2 v = g_sorted[m];
        if (v.x > Ti) s += v.y;
    }

    float num = 0.f, den = 0.f;
    const float tmax = __uint_as_float(g_tmax_bits);
    if (E[i] != 0 && Ti < tmax) {            // strict: ties at max have no risk set
        float pt = g_pe[i] / (s + EPSF);
        num = logf(fmaxf(pt, EPSF));         // upper clip at max(P_tmp) is a no-op
        den = 1.f;
    }
    #pragma unroll
    for (int o = 16; o; o >>= 1) {
        num += __shfl_xor_sync(0xffffffffu, num, o);
        den += __shfl_xor_sync(0xffffffffu, den, o);
    }
    int w = threadIdx.x >> 5, l = threadIdx.x & 31;
    if (l == 0) { rn[w] = num; rd[w] = den; }
    __syncthreads();
    if (threadIdx.x == 0) {
        float n = 0.f, d = 0.f;
        #pragma unroll
        for (int k = 0; k < 8; k++) { n += rn[k]; d += rd[k]; }
        atomicAdd(&g_num, n);
        atomicAdd(&g_den, d);
        __threadfence();
        int done = atomicAdd(&g_done, 1);
        if (done == (int)gridDim.x - 1) {
            float tn = atomicAdd(&g_num, 0.f);   // atomic read-after-fence
            float td = atomicAdd(&g_den, 0.f);
            out[0] = -tn / td;
            g_done = 0;                          // reset for next replay
        }
    }
}

extern "C" void kernel_launch(void* const* d_in, const int* in_sizes, int n_in,
                              void* d_out, int out_size) {
    const float* P_risk = (const float*)d_in[0];
    const float* T      = (const float*)d_in[1];
    const int*   E      = (const int*)d_in[2];
    float* out = (float*)d_out;

    k_init   <<<NB / 256, 256>>>();
    k_pack   <<<N_ELEM / 256, 256>>>(P_risk, T);
    k_scan   <<<1, SCAN_T>>>();
    k_scatter<<<N_ELEM / 256, 256>>>(T);
    k_final  <<<N_ELEM / 256, 256>>>(T, E, out);
}

// round 3
// speedup vs baseline: 2.8274x; 2.5144x over previous
#include <cuda_runtime.h>

// DeepSurvLoss, N=16384 — single fused persistent kernel, O(N).
// 64 blocks x 256 threads = 16384 threads = N elements = NB buckets.
// Software grid barriers (all blocks co-resident: 64 < 148 SMs).
//
//   bucket b = floor(T * 2^14)  (exact & monotone for T in [0,1))
//   P_exp_sum[i] = suffix-sum of per-bucket exp-sums over buckets > b_i
//                + strict-compare pass over bucket b_i's own members
//   loss = -sum(log(max(pe_i/(sum_i+EPS), EPS)) * Ef_i) / sum(Ef_i)

#define N_ELEM 16384
#define NB     16384
#define NBLK   64
#define TPB    256
#define EPSF   1e-6f

__device__ int      g_hist[NB];
__device__ float    g_bsum[NB];
__device__ int      g_offs[NB];
__device__ int      g_cursor[NB];
__device__ float    g_suf[NB];
__device__ float2   g_sorted[N_ELEM];
__device__ int      g_btoti[NBLK];
__device__ float    g_btotf[NBLK];
__device__ float    g_num, g_den;
__device__ unsigned g_tmax_bits;
__device__ unsigned g_bar[8];        // statically zero; reset by last block each call
__device__ int      g_done;          // ditto

__device__ __forceinline__ int bucket_of(float t) {
    int b = (int)(t * 16384.0f);     // *2^14: exact, monotone
    return b > (NB - 1) ? (NB - 1) : b;
}

__device__ __forceinline__ void grid_bar(int idx) {
    __syncthreads();
    if (threadIdx.x == 0) {
        __threadfence();
        atomicAdd(&g_bar[idx], 1u);
        while (*(volatile unsigned*)&g_bar[idx] < NBLK) { }
        __threadfence();
    }
    __syncthreads();
}

__global__ void __launch_bounds__(TPB) k_all(const float* __restrict__ P_risk,
                                             const float* __restrict__ T,
                                             const int*   __restrict__ E,
                                             float* __restrict__ out) {
    const int gb   = blockIdx.x * TPB + threadIdx.x;   // 0..16383
    const int tid  = threadIdx.x;
    const int lane = tid & 31;
    const int w    = tid >> 5;

    __shared__ int   s_wi[8];
    __shared__ float s_wf[8];
    __shared__ int   s_i64[NBLK];
    __shared__ float s_f64[NBLK];
    __shared__ int   s_bbi;
    __shared__ float s_bbf;
    __shared__ float s_rn[8], s_rd[8];

    // ---- phase 0: zero per-call state (1 store/thread) ----
    g_hist[gb] = 0;
    g_bsum[gb] = 0.f;
    if (gb == 0) { g_num = 0.f; g_den = 0.f; g_tmax_bits = 0u; }
    grid_bar(0);

    // ---- phase 1: exp + histogram + bucket sums + max(T) ----
    const float t_i  = T[gb];
    const float pe_i = expf(P_risk[gb]);
    const int   b_i  = bucket_of(t_i);
    atomicAdd(&g_hist[b_i], 1);
    atomicAdd(&g_bsum[b_i], pe_i);
    {
        unsigned tb = __float_as_uint(t_i);   // T >= 0: uint order == float order
        #pragma unroll
        for (int o = 16; o; o >>= 1)
            tb = max(tb, __shfl_xor_sync(0xffffffffu, tb, o));
        if (lane == 0) atomicMax(&g_tmax_bits, tb);
    }
    grid_bar(1);

    // ---- phase 2a: block-local exclusive scans ----
    // int scan over g_hist[gb]; float scan over REVERSED g_bsum (suffix sum,
    // direct sum of positives -> no cancellation).
    const int   h  = g_hist[gb];
    const float fv = g_bsum[NB - 1 - gb];
    int hs = h; float fs = fv;
    #pragma unroll
    for (int o = 1; o < 32; o <<= 1) {
        int   v  = __shfl_up_sync(0xffffffffu, hs, o);
        float vf = __shfl_up_sync(0xffffffffu, fs, o);
        if (lane >= o) { hs += v; fs += vf; }
    }
    if (lane == 31) { s_wi[w] = hs; s_wf[w] = fs; }
    __syncthreads();
    if (tid == 0) {
        int ai = 0; float af = 0.f;
        #pragma unroll
        for (int k = 0; k < 8; k++) {
            int ti = s_wi[k]; float tf = s_wf[k];
            s_wi[k] = ai; s_wf[k] = af;          // exclusive warp bases
            ai += ti; af += tf;
        }
        g_btoti[blockIdx.x] = ai;                // block totals
        g_btotf[blockIdx.x] = af;
    }
    __syncthreads();
    const int   exci = s_wi[w] + (hs - h);
    const float excf = s_wf[w] + (fs - fv);
    grid_bar(2);

    // ---- phase 2b: cross-block bases, write offs/cursor/suf ----
    if (tid < NBLK) { s_i64[tid] = g_btoti[tid]; s_f64[tid] = g_btotf[tid]; }
    __syncthreads();
    if (tid == 0) {
        int ai = 0; float af = 0.f;
        for (int k = 0; k < (int)blockIdx.x; k++) { ai += s_i64[k]; af += s_f64[k]; }
        s_bbi = ai; s_bbf = af;
    }
    __syncthreads();
    {
        const int offs = s_bbi + exci;
        g_offs[gb]   = offs;
        g_cursor[gb] = offs;
        g_suf[NB - 1 - gb] = s_bbf + excf;
    }
    grid_bar(3);

    // ---- phase 3: scatter (t, pe) into bucket-grouped order ----
    {
        const int pos = atomicAdd(&g_cursor[b_i], 1);
        g_sorted[pos] = make_float2(t_i, pe_i);
    }
    grid_bar(4);

    // ---- phase 4: per-element loss + grid reduction ----
    float s = g_suf[b_i];
    {
        const int st = g_offs[b_i];
        const int en = g_cursor[b_i];            // == offs + hist now
        for (int m = st; m < en; m++) {
            float2 v = g_sorted[m];
            if (v.x > t_i) s += v.y;             // strict, exact within bucket
        }
    }
    float num = 0.f, den = 0.f;
    {
        const float tmax = __uint_as_float(g_tmax_bits);
        if (E[gb] != 0 && t_i < tmax) {          // ties at max: empty risk set
            float pt = pe_i / (s + EPSF);
            num = logf(fmaxf(pt, EPSF));         // upper clip is a value no-op
            den = 1.f;
        }
    }
    #pragma unroll
    for (int o = 16; o; o >>= 1) {
        num += __shfl_xor_sync(0xffffffffu, num, o);
        den += __shfl_xor_sync(0xffffffffu, den, o);
    }
    if (lane == 0) { s_rn[w] = num; s_rd[w] = den; }
    __syncthreads();
    if (tid == 0) {
        float n = 0.f, d = 0.f;
        #pragma unroll
        for (int k = 0; k < 8; k++) { n += s_rn[k]; d += s_rd[k]; }
        atomicAdd(&g_num, n);
        atomicAdd(&g_den, d);
        __threadfence();
        int done = atomicAdd(&g_done, 1);
        if (done == NBLK - 1) {
            // all blocks past every spin -> safe to finalize and reset
            float tn = atomicAdd(&g_num, 0.f);
            float td = atomicAdd(&g_den, 0.f);
            out[0] = -tn / td;
            g_done = 0;
            #pragma unroll
            for (int k = 0; k < 8; k++) g_bar[k] = 0u;
        }
    }
}

extern "C" void kernel_launch(void* const* d_in, const int* in_sizes, int n_in,
                              void* d_out, int out_size) {
    const float* P_risk = (const float*)d_in[0];
    const float* T      = (const float*)d_in[1];
    const int*   E      = (const int*)d_in[2];
    float* out = (float*)d_out;

    k_all<<<NBLK, TPB>>>(P_risk, T, E, out);
}